// round 12
// baseline (speedup 1.0000x reference)
#include <cuda_runtime.h>
#include <cuda_fp16.h>
#include <cstdint>

typedef unsigned long long ull;

constexpr int NN = 100000;   // nodes
constexpr int EE = 1600000;  // edges (no self loops)
constexpr int NPB = 592;     // prep blocks: 4/SM, max occupancy, co-resident
constexpr int NSB = 98;      // scan blocks (1024 nodes each)

struct __align__(8) Edge { int s; float w; };

// ---------------- static device scratch --------------------------------------
__device__ int      g_is64;
__device__ int      g_cnt[NN];
__device__ int      g_rowptr[NN + 1];
__device__ int      g_bsum[256];
__device__ float    g_dinv[NN];
__device__ Edge     g_edge[EE];
__device__ float    g_fbuf[(size_t)NN * 12];    // fp32 agg12 output
__device__ __half   g_hA[(size_t)NN * 128];     // fp16 ping
__device__ __half   g_hB[(size_t)NN * 128];     // fp16 pong (holds fp16-x early)
__device__ unsigned g_bcnt[8];                  // grid-barrier counters (self-reset)
__device__ unsigned g_bsense[8];                // grid-barrier senses (monotonic)

// fp16 MMA m16n8k16 (arch-agnostic PTX, sm_80+), fp32 accumulate
__device__ __forceinline__ void mma_f16(float* c, uint32_t a0, uint32_t a1,
                                        uint32_t a2, uint32_t a3,
                                        uint32_t b0, uint32_t b1) {
    asm volatile(
        "mma.sync.aligned.m16n8k16.row.col.f32.f16.f16.f32 "
        "{%0,%1,%2,%3}, {%4,%5,%6,%7}, {%8,%9}, {%0,%1,%2,%3};"
        : "+f"(c[0]), "+f"(c[1]), "+f"(c[2]), "+f"(c[3])
        : "r"(a0), "r"(a1), "r"(a2), "r"(a3), "r"(b0), "r"(b1));
}

__device__ __forceinline__ uint32_t pack_h2(float a, float b) {
    __half2 h = __floats2half2_rn(a, b);
    return *(uint32_t*)&h;
}

// load 8 halfs (16B) -> 8 floats
__device__ __forceinline__ void ld_half8(const __half* p, float* f) {
    uint4 r = *(const uint4*)p;
    const __half2* h2 = (const __half2*)&r;
#pragma unroll
    for (int j = 0; j < 4; j++) {
        float2 t = __half22float2(h2[j]);
        f[2 * j] = t.x; f[2 * j + 1] = t.y;
    }
}

__device__ __forceinline__ int load_idx(const int* __restrict__ w, int pos, int is64) {
    if (is64) return ((const int2*)w)[pos].x;
    return w[pos];
}

// ---------------- software grid barrier (co-resident grids only) -------------
__device__ __forceinline__ void gbar(int slot, int nb) {
    __syncthreads();
    if (threadIdx.x == 0) {
        __threadfence();
        unsigned s = atomicAdd(&g_bsense[slot], 0u);  // read BEFORE arriving
        if (atomicAdd(&g_bcnt[slot], 1u) == (unsigned)nb - 1u) {
            g_bcnt[slot] = 0;
            __threadfence();
            atomicAdd(&g_bsense[slot], 1u);
        } else {
            while (atomicAdd(&g_bsense[slot], 0u) == s) __nanosleep(64);
        }
    }
    __syncthreads();
}

// ---------------- k_prep: zero + detect + x->fp16, barrier, count ------------
__global__ __launch_bounds__(256) void k_prep(const int* __restrict__ w,
                                              const float* __restrict__ x, int E) {
    int b = blockIdx.x, t = threadIdx.x;
    int gid = b * 256 + t;
    const int nthr = NPB * 256;

    // phase 0: zero counts, convert x -> fp16 (into g_hB), detect dtype
    for (int i = gid; i < NN; i += nthr) g_cnt[i] = 0;
    for (int i = gid; i < NN * 12; i += nthr) g_hB[i] = __float2half(x[i]);
    if (b == 0 && t < 32) {
        int acc = 0;
        for (int j = t; j < 1024; j += 32) acc |= w[2 * j + 1];
#pragma unroll
        for (int off = 16; off > 0; off >>= 1)
            acc |= __shfl_xor_sync(0xffffffffu, acc, off);
        if (t == 0) g_is64 = (acc == 0) ? 1 : 0;
    }
    gbar(0, NPB);
    int is64 = g_is64;

    // phase 1: degree count (4-edge vectorized chunks, grid-stride)
    for (int e0 = gid * 4; e0 < E; e0 += nthr * 4) {
        int d[4];
        int nv = min(4, E - e0);
        if (is64) {
            if (nv == 4 && ((E + e0) & 1) == 0) {
                int4 a = *(const int4*)&w[2 * (E + e0)];
                int4 c = *(const int4*)&w[2 * (E + e0) + 4];
                d[0] = a.x; d[1] = a.z; d[2] = c.x; d[3] = c.z;
            } else {
                for (int j = 0; j < nv; j++) d[j] = ((const int2*)w)[E + e0 + j].x;
            }
        } else {
            if (nv == 4 && ((E + e0) & 3) == 0) {
                int4 a = *(const int4*)&w[E + e0];
                d[0] = a.x; d[1] = a.y; d[2] = a.z; d[3] = a.w;
            } else {
                for (int j = 0; j < nv; j++) d[j] = w[E + e0 + j];
            }
        }
        for (int j = 0; j < nv; j++)
            if ((unsigned)d[j] < (unsigned)NN) atomicAdd(&g_cnt[d[j]], 1);
    }
}

// ---------------- k_scanall: scan1+dinv / scan2 / scan3+cursor ---------------
__global__ __launch_bounds__(256) void k_scanall() {
    __shared__ int sh[256];
    int b = blockIdx.x, t = threadIdx.x;
    int base = b * 1024 + t * 4;

    // phase A: per-block sums + dinv
    int v[4];
    int local = 0;
#pragma unroll
    for (int j = 0; j < 4; j++) {
        int i = base + j;
        v[j] = 0;
        if (i < NN) {
            int c = g_cnt[i];
            v[j] = c;
            local += c;
            g_dinv[i] = rsqrtf((float)(c + 1));
        }
    }
    sh[t] = local;
    __syncthreads();
    for (int off = 128; off > 0; off >>= 1) {
        if (t < off) sh[t] += sh[t + off];
        __syncthreads();
    }
    if (t == 0) g_bsum[b] = sh[0];
    gbar(1, NSB);

    // phase B: block 0 exclusive-scans block sums
    if (b == 0) {
        int bv = (t < NSB) ? g_bsum[t] : 0;
        sh[t] = bv;
        __syncthreads();
        for (int off = 1; off < 256; off <<= 1) {
            int tmp = (t >= off) ? sh[t - off] : 0;
            __syncthreads();
            sh[t] += tmp;
            __syncthreads();
        }
        if (t < NSB) g_bsum[t] = sh[t] - bv;
        if (t == 255) g_rowptr[NN] = sh[255];
    }
    gbar(2, NSB);

    // phase C: block-local exclusive scan -> rowptr + cursor
    sh[t] = local;
    __syncthreads();
    for (int off = 1; off < 256; off <<= 1) {
        int tmp = (t >= off) ? sh[t - off] : 0;
        __syncthreads();
        sh[t] += tmp;
        __syncthreads();
    }
    int excl = g_bsum[b] + sh[t] - local;
#pragma unroll
    for (int j = 0; j < 4; j++) {
        int i = base + j;
        if (i < NN) { g_rowptr[i] = excl; g_cnt[i] = excl; }
        excl += v[j];
    }
}

// ---------------- scatter (full-occupancy standalone; R8-proven) -------------
__global__ void k_scatter(const int* __restrict__ w, int E) {
    int e0 = (blockIdx.x * blockDim.x + threadIdx.x) * 2;
    if (e0 >= E) return;
    int is64 = g_is64;
    int nv = min(2, E - e0);
    int s[2], d[2];
    if (is64) {
        if (nv == 2 && ((E + e0) & 1) == 0) {
            int4 a = *(const int4*)&w[2 * e0];
            int4 b = *(const int4*)&w[2 * (E + e0)];
            s[0] = a.x; s[1] = a.z; d[0] = b.x; d[1] = b.z;
        } else {
            for (int j = 0; j < nv; j++) {
                s[j] = ((const int2*)w)[e0 + j].x;
                d[j] = ((const int2*)w)[E + e0 + j].x;
            }
        }
    } else {
        if (nv == 2 && ((E + e0) & 1) == 0) {
            int2 a = *(const int2*)&w[e0];
            int2 b = *(const int2*)&w[E + e0];
            s[0] = a.x; s[1] = a.y; d[0] = b.x; d[1] = b.y;
        } else {
            for (int j = 0; j < nv; j++) { s[j] = w[e0 + j]; d[j] = w[E + e0 + j]; }
        }
    }
    for (int j = 0; j < nv; j++) {
        if ((unsigned)s[j] < (unsigned)NN && (unsigned)d[j] < (unsigned)NN) {
            int pos = atomicAdd(&g_cnt[d[j]], 1);
            Edge ed; ed.s = s[j]; ed.w = g_dinv[s[j]] * g_dinv[d[j]];
            g_edge[pos] = ed;
        }
    }
}

// ---------------- agg12: fp16 gather (x in g_hB) -> g_fbuf fp32 --------------
__global__ void k_agg12() {
    constexpr int CH = 12, GRP = 8;
    const __half* __restrict__ xh = g_hB;
    int node = (blockIdx.x * blockDim.x + threadIdx.x) / GRP;
    int sub = threadIdx.x % GRP;
    if (node >= NN) return;
    bool act = sub < 6;               // 6 lanes x 2 halfs = 12 ch
    int c0 = sub * 2;

    float a0 = 0.f, a1 = 0.f;
    float sd = g_dinv[node];
    sd *= sd;
    if (act) {
        __half2 h = *(const __half2*)&xh[(size_t)node * CH + c0];
        float2 f = __half22float2(h);
        a0 = sd * f.x; a1 = sd * f.y;
    }
    int e = g_rowptr[node];
    const int end = g_rowptr[node + 1];
    for (; e + 2 <= end; e += 2) {
        Edge e0 = g_edge[e];
        Edge e1 = g_edge[e + 1];
        if (act) {
            float2 f0 = __half22float2(*(const __half2*)&xh[(size_t)e0.s * CH + c0]);
            float2 f1 = __half22float2(*(const __half2*)&xh[(size_t)e1.s * CH + c0]);
            a0 += e0.w * f0.x + e1.w * f1.x;
            a1 += e0.w * f0.y + e1.w * f1.y;
        }
    }
    if (e < end) {
        Edge e0 = g_edge[e];
        if (act) {
            float2 f0 = __half22float2(*(const __half2*)&xh[(size_t)e0.s * CH + c0]);
            a0 += e0.w * f0.x;
            a1 += e0.w * f0.y;
        }
    }
    if (act) *(float2*)&g_fbuf[(size_t)node * CH + c0] = make_float2(a0, a1);
}

// ---------------- GEMM1 scalar: g_fbuf 12 -> 64 (+b1, relu) -> g_hA fp16 -----
__global__ __launch_bounds__(128) void k_gemm1(const float* __restrict__ W,
                                               const float* __restrict__ bias) {
    constexpr int IN = 12, OUT = 64, BN = 32, HS = BN + 4;
    __shared__ float Wsm[IN * OUT];
    __shared__ float Hsm[IN * HS];
    int tid = threadIdx.x;
    int n0blk = blockIdx.x * BN;

    for (int i = tid; i < IN * OUT; i += 128) Wsm[i] = W[i];
    for (int i = tid; i < BN * IN; i += 128) {
        int n = i / IN, k = i % IN;
        int node = n0blk + n;
        Hsm[k * HS + n] = (node < NN) ? g_fbuf[(size_t)node * IN + k] : 0.f;
    }
    __syncthreads();

    int tx = tid & 15, ty = tid >> 4;
    int c0 = tx * 4, n0 = ty * 4;
    float acc[4][4];
#pragma unroll
    for (int a = 0; a < 4; a++)
#pragma unroll
        for (int c = 0; c < 4; c++) acc[a][c] = 0.f;
#pragma unroll
    for (int k = 0; k < IN; k++) {
        float4 hv4 = *(const float4*)&Hsm[k * HS + n0];
        float4 wv4 = *(const float4*)&Wsm[k * OUT + c0];
        float hv[4] = {hv4.x, hv4.y, hv4.z, hv4.w};
        float wv[4] = {wv4.x, wv4.y, wv4.z, wv4.w};
#pragma unroll
        for (int a = 0; a < 4; a++)
#pragma unroll
            for (int c = 0; c < 4; c++) acc[a][c] += hv[a] * wv[c];
    }
    float4 b4 = *(const float4*)&bias[c0];
#pragma unroll
    for (int a = 0; a < 4; a++) {
        int node = n0blk + n0 + a;
        if (node < NN) {
            float t0 = fmaxf(acc[a][0] + b4.x, 0.f);
            float t1 = fmaxf(acc[a][1] + b4.y, 0.f);
            float t2 = fmaxf(acc[a][2] + b4.z, 0.f);
            float t3 = fmaxf(acc[a][3] + b4.w, 0.f);
            *(__half2*)&g_hA[(size_t)node * OUT + c0] = __floats2half2_rn(t0, t1);
            *(__half2*)&g_hA[(size_t)node * OUT + c0 + 2] = __floats2half2_rn(t2, t3);
        }
    }
}

// ---------------- agg64: fp16 gather g_hA -> fp16 g_hB (fp32 accum) ----------
__global__ void k_agg64() {
    constexpr int CH = 64, GRP = 8, VEC = 8;
    const __half* __restrict__ hh = g_hA;
    int node = (blockIdx.x * blockDim.x + threadIdx.x) / GRP;
    int sub = threadIdx.x % GRP;
    if (node >= NN) return;
    int c0 = sub * VEC;

    float acc[VEC];
    float sd = g_dinv[node];
    sd *= sd;
    {
        float f[VEC];
        ld_half8(hh + (size_t)node * CH + c0, f);
#pragma unroll
        for (int v = 0; v < VEC; v++) acc[v] = sd * f[v];
    }
    int e = g_rowptr[node];
    const int end = g_rowptr[node + 1];
    for (; e + 2 <= end; e += 2) {
        Edge e0 = g_edge[e];
        Edge e1 = g_edge[e + 1];
        float f0[VEC], f1[VEC];
        ld_half8(hh + (size_t)e0.s * CH + c0, f0);
        ld_half8(hh + (size_t)e1.s * CH + c0, f1);
#pragma unroll
        for (int v = 0; v < VEC; v++) acc[v] += e0.w * f0[v] + e1.w * f1[v];
    }
    if (e < end) {
        Edge e0 = g_edge[e];
        float f0[VEC];
        ld_half8(hh + (size_t)e0.s * CH + c0, f0);
#pragma unroll
        for (int v = 0; v < VEC; v++) acc[v] += e0.w * f0[v];
    }
    uint4 o;
    o.x = pack_h2(acc[0], acc[1]); o.y = pack_h2(acc[2], acc[3]);
    o.z = pack_h2(acc[4], acc[5]); o.w = pack_h2(acc[6], acc[7]);
    *(uint4*)&g_hB[(size_t)node * CH + c0] = o;
}

// ---------------- fp16 MMA GEMM: src fp16 [128,K] @ W[K,OUT] -----------------
template <int K, int OUT, bool SRC_A, bool DST_A, bool BIAS, bool RELU>
__global__ __launch_bounds__(256) void k_hgemm(const float* __restrict__ W,
                                               const float* __restrict__ bias) {
    const __half* __restrict__ src = SRC_A ? (const __half*)g_hA : (const __half*)g_hB;
    __half* __restrict__ dst = DST_A ? (__half*)g_hA : (__half*)g_hB;
    constexpr int KC = 64;
    constexpr int NCH = K / KC;
    constexpr int AS = 36;
    constexpr int BS = 36;
    constexpr int NT = OUT / 8;
    __shared__ uint32_t Asm[128 * AS];
    __shared__ uint32_t Bsm[OUT * BS];

    int tid = threadIdx.x;
    int wid = tid >> 5, lane = tid & 31;
    int g = lane >> 2, t4 = lane & 3;
    int tile0 = blockIdx.x * 128;

    float acc[NT][4];
#pragma unroll
    for (int nt = 0; nt < NT; nt++)
#pragma unroll
        for (int j = 0; j < 4; j++) acc[nt][j] = 0.f;

    for (int c = 0; c < NCH; c++) {
        int kc = c * KC;
        for (int i = tid; i < 128 * 8; i += 256) {
            int row = i >> 3, j = i & 7;
            int node = tile0 + row;
            uint4 v = make_uint4(0u, 0u, 0u, 0u);
            if (node < NN) v = *(const uint4*)&src[(size_t)node * K + kc + 8 * j];
            *(uint4*)&Asm[row * AS + 4 * j] = v;
        }
        for (int i = tid; i < OUT * 32; i += 256) {
            int col = i % OUT, kk = i / OUT;
            float w0 = W[(size_t)(kc + 2 * kk) * OUT + col];
            float w1 = W[(size_t)(kc + 2 * kk + 1) * OUT + col];
            Bsm[col * BS + kk] = pack_h2(w0, w1);
        }
        __syncthreads();

#pragma unroll
        for (int ks = 0; ks < KC / 16; ks++) {
            int ko = ks * 8;
            const uint32_t* ar0 = &Asm[(wid * 16 + g) * AS + ko + t4];
            const uint32_t* ar1 = &Asm[(wid * 16 + g + 8) * AS + ko + t4];
            uint32_t a0 = ar0[0], a1 = ar1[0], a2 = ar0[4], a3 = ar1[4];
#pragma unroll
            for (int nt = 0; nt < NT; nt++) {
                uint32_t b0 = Bsm[(nt * 8 + g) * BS + ko + t4];
                uint32_t b1 = Bsm[(nt * 8 + g) * BS + ko + t4 + 4];
                mma_f16(acc[nt], a0, a1, a2, a3, b0, b1);
            }
        }
        __syncthreads();
    }

    int node0 = tile0 + wid * 16 + g;
    int node1 = node0 + 8;
#pragma unroll
    for (int nt = 0; nt < NT; nt++) {
        int col = nt * 8 + 2 * t4;
        float2 bv = make_float2(0.f, 0.f);
        if (BIAS) bv = *(const float2*)&bias[col];
        float o0x = acc[nt][0] + bv.x, o0y = acc[nt][1] + bv.y;
        float o1x = acc[nt][2] + bv.x, o1y = acc[nt][3] + bv.y;
        if (RELU) {
            o0x = fmaxf(o0x, 0.f); o0y = fmaxf(o0y, 0.f);
            o1x = fmaxf(o1x, 0.f); o1y = fmaxf(o1y, 0.f);
        }
        if (node0 < NN)
            *(__half2*)&dst[(size_t)node0 * OUT + col] = __floats2half2_rn(o0x, o0y);
        if (node1 < NN)
            *(__half2*)&dst[(size_t)node1 * OUT + col] = __floats2half2_rn(o1x, o1y);
    }
}

// ---------------- agg96: fp16 gather g_hB (+b3) -> fp32 out ------------------
__global__ void k_agg96(float* __restrict__ out, const float* __restrict__ bias) {
    constexpr int CH = 96, GRP = 16, VEC = 8;
    const __half* __restrict__ hh = g_hB;
    int node = (blockIdx.x * blockDim.x + threadIdx.x) / GRP;
    int sub = threadIdx.x % GRP;
    if (node >= NN) return;
    bool act = sub < (CH / VEC);   // 12 of 16
    int c0 = sub * VEC;

    float acc[VEC];
#pragma unroll
    for (int v = 0; v < VEC; v++) acc[v] = 0.f;

    float sd = g_dinv[node];
    sd *= sd;
    if (act) {
        float f[VEC];
        ld_half8(hh + (size_t)node * CH + c0, f);
#pragma unroll
        for (int v = 0; v < VEC; v++) acc[v] = sd * f[v];
    }
    int e = g_rowptr[node];
    const int end = g_rowptr[node + 1];
    for (; e + 2 <= end; e += 2) {
        Edge e0 = g_edge[e];
        Edge e1 = g_edge[e + 1];
        if (act) {
            float f0[VEC], f1[VEC];
            ld_half8(hh + (size_t)e0.s * CH + c0, f0);
            ld_half8(hh + (size_t)e1.s * CH + c0, f1);
#pragma unroll
            for (int v = 0; v < VEC; v++) acc[v] += e0.w * f0[v] + e1.w * f1[v];
        }
    }
    if (e < end) {
        Edge e0 = g_edge[e];
        if (act) {
            float f0[VEC];
            ld_half8(hh + (size_t)e0.s * CH + c0, f0);
#pragma unroll
            for (int v = 0; v < VEC; v++) acc[v] += e0.w * f0[v];
        }
    }
    if (act) {
        float* orow = out + (size_t)node * CH + c0;
#pragma unroll
        for (int v = 0; v < VEC; v++) acc[v] += bias[c0 + v];
        *(float4*)&orow[0] = make_float4(acc[0], acc[1], acc[2], acc[3]);
        *(float4*)&orow[4] = make_float4(acc[4], acc[5], acc[6], acc[7]);
    }
}

// ---------------- launch ------------------------------------------------------
extern "C" void kernel_launch(void* const* d_in, const int* in_sizes, int n_in,
                              void* d_out, int out_size) {
    const float* x  = (const float*)d_in[0];
    const int* ei32 = (const int*)d_in[1];
    const float* W1 = (const float*)d_in[2];
    const float* b1 = (const float*)d_in[3];
    const float* W2 = (const float*)d_in[4];
    const float* b2 = (const float*)d_in[5];
    const float* W3 = (const float*)d_in[6];
    const float* b3 = (const float*)d_in[7];
    float* out      = (float*)d_out;
    int E = in_sizes[1] / 2;

    // CSR build: 3 kernels (prep w/ count @ 4 blocks/SM, fused scans, scatter)
    k_prep<<<NPB, 256>>>(ei32, x, E);
    k_scanall<<<NSB, 256>>>();
    k_scatter<<<(E / 2 + 255) / 256, 256>>>(ei32, E);

    int gMMA = (NN + 127) / 128;  // 782

    // layer 1: agg12(fp16 x) -> fbuf -> scalar GEMM 12->64 (+b1, relu) -> hA
    k_agg12<<<(NN * 8 + 255) / 256, 256>>>();
    k_gemm1<<<(NN + 31) / 32, 128>>>(W1, b1);

    // layer 2: agg64 hA->hB -> f16 MMA 64->128 (+b2, relu) -> hA
    k_agg64<<<(NN * 8 + 255) / 256, 256>>>();
    k_hgemm<64, 128, false, true, true, true><<<gMMA, 256>>>(W2, b2);

    // layer 3: f16 MMA 128->96 hA->hB -> agg96 (+b3) -> out fp32
    k_hgemm<128, 96, true, false, false, false><<<gMMA, 256>>>(W3, nullptr);
    k_agg96<<<(NN * 16 + 255) / 256, 256>>>(out, b3);
}

// round 13
// speedup vs baseline: 1.0315x; 1.0315x over previous
#include <cuda_runtime.h>
#include <cuda_fp16.h>
#include <cstdint>

typedef unsigned long long ull;

constexpr int NN = 100000;   // nodes
constexpr int EE = 1600000;  // edges (no self loops)
constexpr int NPB = 592;     // prep blocks: 4/SM, co-resident
constexpr int NSB = 98;      // scan blocks (1024 nodes each)

struct __align__(8) Edge { int s; float w; };

// ---------------- static device scratch --------------------------------------
__device__ int      g_is64;
__device__ int      g_cnt[NN];
__device__ int      g_rowptr[NN + 1];
__device__ int      g_bsum[256];
__device__ float    g_dinv[NN];
__device__ Edge     g_edge[EE];
__device__ float    g_fbuf[(size_t)NN * 12];
__device__ __half   g_hA[(size_t)NN * 128];
__device__ __half   g_hB[(size_t)NN * 128];
__device__ unsigned g_bcnt[8];
__device__ unsigned g_bsense[8];

// fp16 MMA m16n8k16 (arch-agnostic PTX, sm_80+), fp32 accumulate
__device__ __forceinline__ void mma_f16(float* c, uint32_t a0, uint32_t a1,
                                        uint32_t a2, uint32_t a3,
                                        uint32_t b0, uint32_t b1) {
    asm volatile(
        "mma.sync.aligned.m16n8k16.row.col.f32.f16.f16.f32 "
        "{%0,%1,%2,%3}, {%4,%5,%6,%7}, {%8,%9}, {%0,%1,%2,%3};"
        : "+f"(c[0]), "+f"(c[1]), "+f"(c[2]), "+f"(c[3])
        : "r"(a0), "r"(a1), "r"(a2), "r"(a3), "r"(b0), "r"(b1));
}

__device__ __forceinline__ uint32_t pack_h2(float a, float b) {
    __half2 h = __floats2half2_rn(a, b);
    return *(uint32_t*)&h;
}

__device__ __forceinline__ void ld_half8(const __half* p, float* f) {
    uint4 r = *(const uint4*)p;
    const __half2* h2 = (const __half2*)&r;
#pragma unroll
    for (int j = 0; j < 4; j++) {
        float2 t = __half22float2(h2[j]);
        f[2 * j] = t.x; f[2 * j + 1] = t.y;
    }
}

__device__ __forceinline__ int load_idx(const int* __restrict__ w, int pos, int is64) {
    if (is64) return ((const int2*)w)[pos].x;
    return w[pos];
}

// ---------------- software grid barrier (co-resident grids only) -------------
__device__ __forceinline__ void gbar(int slot, int nb) {
    __syncthreads();
    if (threadIdx.x == 0) {
        __threadfence();
        unsigned s = atomicAdd(&g_bsense[slot], 0u);
        if (atomicAdd(&g_bcnt[slot], 1u) == (unsigned)nb - 1u) {
            g_bcnt[slot] = 0;
            __threadfence();
            atomicAdd(&g_bsense[slot], 1u);
        } else {
            while (atomicAdd(&g_bsense[slot], 0u) == s) __nanosleep(64);
        }
    }
    __syncthreads();
}

// ---------------- k_prep: zero + detect + x->fp16, barrier, count ------------
__global__ __launch_bounds__(256) void k_prep(const int* __restrict__ w,
                                              const float* __restrict__ x, int E) {
    int b = blockIdx.x, t = threadIdx.x;
    int gid = b * 256 + t;
    const int nthr = NPB * 256;

    for (int i = gid; i < NN; i += nthr) g_cnt[i] = 0;
    for (int i = gid; i < NN * 12; i += nthr) g_hB[i] = __float2half(x[i]);
    if (b == 0 && t < 32) {
        int acc = 0;
        for (int j = t; j < 1024; j += 32) acc |= w[2 * j + 1];
#pragma unroll
        for (int off = 16; off > 0; off >>= 1)
            acc |= __shfl_xor_sync(0xffffffffu, acc, off);
        if (t == 0) g_is64 = (acc == 0) ? 1 : 0;
    }
    gbar(0, NPB);
    int is64 = g_is64;

    for (int e0 = gid * 4; e0 < E; e0 += nthr * 4) {
        int d[4];
        int nv = min(4, E - e0);
        if (is64) {
            if (nv == 4 && ((E + e0) & 1) == 0) {
                int4 a = *(const int4*)&w[2 * (E + e0)];
                int4 c = *(const int4*)&w[2 * (E + e0) + 4];
                d[0] = a.x; d[1] = a.z; d[2] = c.x; d[3] = c.z;
            } else {
                for (int j = 0; j < nv; j++) d[j] = ((const int2*)w)[E + e0 + j].x;
            }
        } else {
            if (nv == 4 && ((E + e0) & 3) == 0) {
                int4 a = *(const int4*)&w[E + e0];
                d[0] = a.x; d[1] = a.y; d[2] = a.z; d[3] = a.w;
            } else {
                for (int j = 0; j < nv; j++) d[j] = w[E + e0 + j];
            }
        }
        for (int j = 0; j < nv; j++)
            if ((unsigned)d[j] < (unsigned)NN) atomicAdd(&g_cnt[d[j]], 1);
    }
}

// ---------------- k_scanall: scan1+dinv / scan2 / scan3+cursor ---------------
__global__ __launch_bounds__(256) void k_scanall() {
    __shared__ int sh[256];
    int b = blockIdx.x, t = threadIdx.x;
    int base = b * 1024 + t * 4;

    int v[4];
    int local = 0;
#pragma unroll
    for (int j = 0; j < 4; j++) {
        int i = base + j;
        v[j] = 0;
        if (i < NN) {
            int c = g_cnt[i];
            v[j] = c;
            local += c;
            g_dinv[i] = rsqrtf((float)(c + 1));
        }
    }
    sh[t] = local;
    __syncthreads();
    for (int off = 128; off > 0; off >>= 1) {
        if (t < off) sh[t] += sh[t + off];
        __syncthreads();
    }
    if (t == 0) g_bsum[b] = sh[0];
    gbar(1, NSB);

    if (b == 0) {
        int bv = (t < NSB) ? g_bsum[t] : 0;
        sh[t] = bv;
        __syncthreads();
        for (int off = 1; off < 256; off <<= 1) {
            int tmp = (t >= off) ? sh[t - off] : 0;
            __syncthreads();
            sh[t] += tmp;
            __syncthreads();
        }
        if (t < NSB) g_bsum[t] = sh[t] - bv;
        if (t == 255) g_rowptr[NN] = sh[255];
    }
    gbar(2, NSB);

    sh[t] = local;
    __syncthreads();
    for (int off = 1; off < 256; off <<= 1) {
        int tmp = (t >= off) ? sh[t - off] : 0;
        __syncthreads();
        sh[t] += tmp;
        __syncthreads();
    }
    int excl = g_bsum[b] + sh[t] - local;
#pragma unroll
    for (int j = 0; j < 4; j++) {
        int i = base + j;
        if (i < NN) { g_rowptr[i] = excl; g_cnt[i] = excl; }
        excl += v[j];
    }
}

// ---------------- scatter (full-occupancy standalone) ------------------------
__global__ void k_scatter(const int* __restrict__ w, int E) {
    int e0 = (blockIdx.x * blockDim.x + threadIdx.x) * 2;
    if (e0 >= E) return;
    int is64 = g_is64;
    int nv = min(2, E - e0);
    int s[2], d[2];
    if (is64) {
        if (nv == 2 && ((E + e0) & 1) == 0) {
            int4 a = *(const int4*)&w[2 * e0];
            int4 b = *(const int4*)&w[2 * (E + e0)];
            s[0] = a.x; s[1] = a.z; d[0] = b.x; d[1] = b.z;
        } else {
            for (int j = 0; j < nv; j++) {
                s[j] = ((const int2*)w)[e0 + j].x;
                d[j] = ((const int2*)w)[E + e0 + j].x;
            }
        }
    } else {
        if (nv == 2 && ((E + e0) & 1) == 0) {
            int2 a = *(const int2*)&w[e0];
            int2 b = *(const int2*)&w[E + e0];
            s[0] = a.x; s[1] = a.y; d[0] = b.x; d[1] = b.y;
        } else {
            for (int j = 0; j < nv; j++) { s[j] = w[e0 + j]; d[j] = w[E + e0 + j]; }
        }
    }
    for (int j = 0; j < nv; j++) {
        if ((unsigned)s[j] < (unsigned)NN && (unsigned)d[j] < (unsigned)NN) {
            int pos = atomicAdd(&g_cnt[d[j]], 1);
            Edge ed; ed.s = s[j]; ed.w = g_dinv[s[j]] * g_dinv[d[j]];
            g_edge[pos] = ed;
        }
    }
}

// ---------------- agg12: fp16 gather (x in g_hB) -> g_fbuf fp32, 4-edge MLP --
__global__ void k_agg12() {
    constexpr int CH = 12, GRP = 8;
    const __half* __restrict__ xh = g_hB;
    int node = (blockIdx.x * blockDim.x + threadIdx.x) / GRP;
    int sub = threadIdx.x % GRP;
    if (node >= NN) return;
    bool act = sub < 6;
    int c0 = sub * 2;

    float a0 = 0.f, a1 = 0.f;
    float sd = g_dinv[node];
    sd *= sd;
    if (act) {
        float2 f = __half22float2(*(const __half2*)&xh[(size_t)node * CH + c0]);
        a0 = sd * f.x; a1 = sd * f.y;
    }
    int e = g_rowptr[node];
    const int end = g_rowptr[node + 1];
    for (; e + 4 <= end; e += 4) {
        Edge e0 = g_edge[e],     e1 = g_edge[e + 1];
        Edge e2 = g_edge[e + 2], e3 = g_edge[e + 3];
        if (act) {
            float2 f0 = __half22float2(*(const __half2*)&xh[(size_t)e0.s * CH + c0]);
            float2 f1 = __half22float2(*(const __half2*)&xh[(size_t)e1.s * CH + c0]);
            float2 f2 = __half22float2(*(const __half2*)&xh[(size_t)e2.s * CH + c0]);
            float2 f3 = __half22float2(*(const __half2*)&xh[(size_t)e3.s * CH + c0]);
            a0 += e0.w * f0.x + e1.w * f1.x;
            a1 += e0.w * f0.y + e1.w * f1.y;
            a0 += e2.w * f2.x + e3.w * f3.x;
            a1 += e2.w * f2.y + e3.w * f3.y;
        }
    }
    for (; e < end; e++) {
        Edge e0 = g_edge[e];
        if (act) {
            float2 f0 = __half22float2(*(const __half2*)&xh[(size_t)e0.s * CH + c0]);
            a0 += e0.w * f0.x;
            a1 += e0.w * f0.y;
        }
    }
    if (act) *(float2*)&g_fbuf[(size_t)node * CH + c0] = make_float2(a0, a1);
}

// ---------------- GEMM1 scalar: g_fbuf 12 -> 64 (+b1, relu) -> g_hA fp16 -----
__global__ __launch_bounds__(128) void k_gemm1(const float* __restrict__ W,
                                               const float* __restrict__ bias) {
    constexpr int IN = 12, OUT = 64, BN = 32, HS = BN + 4;
    __shared__ float Wsm[IN * OUT];
    __shared__ float Hsm[IN * HS];
    int tid = threadIdx.x;
    int n0blk = blockIdx.x * BN;

    for (int i = tid; i < IN * OUT; i += 128) Wsm[i] = W[i];
    for (int i = tid; i < BN * IN; i += 128) {
        int n = i / IN, k = i % IN;
        int node = n0blk + n;
        Hsm[k * HS + n] = (node < NN) ? g_fbuf[(size_t)node * IN + k] : 0.f;
    }
    __syncthreads();

    int tx = tid & 15, ty = tid >> 4;
    int c0 = tx * 4, n0 = ty * 4;
    float acc[4][4];
#pragma unroll
    for (int a = 0; a < 4; a++)
#pragma unroll
        for (int c = 0; c < 4; c++) acc[a][c] = 0.f;
#pragma unroll
    for (int k = 0; k < IN; k++) {
        float4 hv4 = *(const float4*)&Hsm[k * HS + n0];
        float4 wv4 = *(const float4*)&Wsm[k * OUT + c0];
        float hv[4] = {hv4.x, hv4.y, hv4.z, hv4.w};
        float wv[4] = {wv4.x, wv4.y, wv4.z, wv4.w};
#pragma unroll
        for (int a = 0; a < 4; a++)
#pragma unroll
            for (int c = 0; c < 4; c++) acc[a][c] += hv[a] * wv[c];
    }
    float4 b4 = *(const float4*)&bias[c0];
#pragma unroll
    for (int a = 0; a < 4; a++) {
        int node = n0blk + n0 + a;
        if (node < NN) {
            float t0 = fmaxf(acc[a][0] + b4.x, 0.f);
            float t1 = fmaxf(acc[a][1] + b4.y, 0.f);
            float t2 = fmaxf(acc[a][2] + b4.z, 0.f);
            float t3 = fmaxf(acc[a][3] + b4.w, 0.f);
            *(__half2*)&g_hA[(size_t)node * OUT + c0] = __floats2half2_rn(t0, t1);
            *(__half2*)&g_hA[(size_t)node * OUT + c0 + 2] = __floats2half2_rn(t2, t3);
        }
    }
}

// ---------------- agg64: fp16 gather g_hA -> g_hB, 4-edge MLP ----------------
__global__ void k_agg64() {
    constexpr int CH = 64, GRP = 8, VEC = 8;
    const __half* __restrict__ hh = g_hA;
    int node = (blockIdx.x * blockDim.x + threadIdx.x) / GRP;
    int sub = threadIdx.x % GRP;
    if (node >= NN) return;
    int c0 = sub * VEC;

    float acc[VEC];
    float sd = g_dinv[node];
    sd *= sd;
    {
        float f[VEC];
        ld_half8(hh + (size_t)node * CH + c0, f);
#pragma unroll
        for (int v = 0; v < VEC; v++) acc[v] = sd * f[v];
    }
    int e = g_rowptr[node];
    const int end = g_rowptr[node + 1];
    for (; e + 4 <= end; e += 4) {
        Edge e0 = g_edge[e],     e1 = g_edge[e + 1];
        Edge e2 = g_edge[e + 2], e3 = g_edge[e + 3];
        float f0[VEC], f1[VEC], f2[VEC], f3[VEC];
        ld_half8(hh + (size_t)e0.s * CH + c0, f0);
        ld_half8(hh + (size_t)e1.s * CH + c0, f1);
        ld_half8(hh + (size_t)e2.s * CH + c0, f2);
        ld_half8(hh + (size_t)e3.s * CH + c0, f3);
#pragma unroll
        for (int v = 0; v < VEC; v++) {
            acc[v] += e0.w * f0[v] + e1.w * f1[v];
            acc[v] += e2.w * f2[v] + e3.w * f3[v];
        }
    }
    for (; e < end; e++) {
        Edge e0 = g_edge[e];
        float f0[VEC];
        ld_half8(hh + (size_t)e0.s * CH + c0, f0);
#pragma unroll
        for (int v = 0; v < VEC; v++) acc[v] += e0.w * f0[v];
    }
    uint4 o;
    o.x = pack_h2(acc[0], acc[1]); o.y = pack_h2(acc[2], acc[3]);
    o.z = pack_h2(acc[4], acc[5]); o.w = pack_h2(acc[6], acc[7]);
    *(uint4*)&g_hB[(size_t)node * CH + c0] = o;
}

// ---------------- fp16 MMA GEMM: src fp16 [128,K] @ W[K,OUT] -----------------
template <int K, int OUT, bool SRC_A, bool DST_A, bool BIAS, bool RELU>
__global__ __launch_bounds__(256) void k_hgemm(const float* __restrict__ W,
                                               const float* __restrict__ bias) {
    const __half* __restrict__ src = SRC_A ? (const __half*)g_hA : (const __half*)g_hB;
    __half* __restrict__ dst = DST_A ? (__half*)g_hA : (__half*)g_hB;
    constexpr int KC = 64;
    constexpr int NCH = K / KC;
    constexpr int AS = 36;
    constexpr int BS = 36;
    constexpr int NT = OUT / 8;
    __shared__ uint32_t Asm[128 * AS];
    __shared__ uint32_t Bsm[OUT * BS];

    int tid = threadIdx.x;
    int wid = tid >> 5, lane = tid & 31;
    int g = lane >> 2, t4 = lane & 3;
    int tile0 = blockIdx.x * 128;

    float acc[NT][4];
#pragma unroll
    for (int nt = 0; nt < NT; nt++)
#pragma unroll
        for (int j = 0; j < 4; j++) acc[nt][j] = 0.f;

    for (int c = 0; c < NCH; c++) {
        int kc = c * KC;
        for (int i = tid; i < 128 * 8; i += 256) {
            int row = i >> 3, j = i & 7;
            int node = tile0 + row;
            uint4 v = make_uint4(0u, 0u, 0u, 0u);
            if (node < NN) v = *(const uint4*)&src[(size_t)node * K + kc + 8 * j];
            *(uint4*)&Asm[row * AS + 4 * j] = v;
        }
        for (int i = tid; i < OUT * 32; i += 256) {
            int col = i % OUT, kk = i / OUT;
            float w0 = W[(size_t)(kc + 2 * kk) * OUT + col];
            float w1 = W[(size_t)(kc + 2 * kk + 1) * OUT + col];
            Bsm[col * BS + kk] = pack_h2(w0, w1);
        }
        __syncthreads();

#pragma unroll
        for (int ks = 0; ks < KC / 16; ks++) {
            int ko = ks * 8;
            const uint32_t* ar0 = &Asm[(wid * 16 + g) * AS + ko + t4];
            const uint32_t* ar1 = &Asm[(wid * 16 + g + 8) * AS + ko + t4];
            uint32_t a0 = ar0[0], a1 = ar1[0], a2 = ar0[4], a3 = ar1[4];
#pragma unroll
            for (int nt = 0; nt < NT; nt++) {
                uint32_t b0 = Bsm[(nt * 8 + g) * BS + ko + t4];
                uint32_t b1 = Bsm[(nt * 8 + g) * BS + ko + t4 + 4];
                mma_f16(acc[nt], a0, a1, a2, a3, b0, b1);
            }
        }
        __syncthreads();
    }

    int node0 = tile0 + wid * 16 + g;
    int node1 = node0 + 8;
#pragma unroll
    for (int nt = 0; nt < NT; nt++) {
        int col = nt * 8 + 2 * t4;
        float2 bv = make_float2(0.f, 0.f);
        if (BIAS) bv = *(const float2*)&bias[col];
        float o0x = acc[nt][0] + bv.x, o0y = acc[nt][1] + bv.y;
        float o1x = acc[nt][2] + bv.x, o1y = acc[nt][3] + bv.y;
        if (RELU) {
            o0x = fmaxf(o0x, 0.f); o0y = fmaxf(o0y, 0.f);
            o1x = fmaxf(o1x, 0.f); o1y = fmaxf(o1y, 0.f);
        }
        if (node0 < NN)
            *(__half2*)&dst[(size_t)node0 * OUT + col] = __floats2half2_rn(o0x, o0y);
        if (node1 < NN)
            *(__half2*)&dst[(size_t)node1 * OUT + col] = __floats2half2_rn(o1x, o1y);
    }
}

// ---------------- agg96: fp16 gather g_hB (+b3) -> fp32 out, 4-edge MLP ------
__global__ void k_agg96(float* __restrict__ out, const float* __restrict__ bias) {
    constexpr int CH = 96, GRP = 16, VEC = 8;
    const __half* __restrict__ hh = g_hB;
    int node = (blockIdx.x * blockDim.x + threadIdx.x) / GRP;
    int sub = threadIdx.x % GRP;
    if (node >= NN) return;
    bool act = sub < (CH / VEC);   // 12 of 16
    int c0 = sub * VEC;

    float acc[VEC];
#pragma unroll
    for (int v = 0; v < VEC; v++) acc[v] = 0.f;

    float sd = g_dinv[node];
    sd *= sd;
    if (act) {
        float f[VEC];
        ld_half8(hh + (size_t)node * CH + c0, f);
#pragma unroll
        for (int v = 0; v < VEC; v++) acc[v] = sd * f[v];
    }
    int e = g_rowptr[node];
    const int end = g_rowptr[node + 1];
    for (; e + 4 <= end; e += 4) {
        Edge e0 = g_edge[e],     e1 = g_edge[e + 1];
        Edge e2 = g_edge[e + 2], e3 = g_edge[e + 3];
        if (act) {
            float f0[VEC], f1[VEC], f2[VEC], f3[VEC];
            ld_half8(hh + (size_t)e0.s * CH + c0, f0);
            ld_half8(hh + (size_t)e1.s * CH + c0, f1);
            ld_half8(hh + (size_t)e2.s * CH + c0, f2);
            ld_half8(hh + (size_t)e3.s * CH + c0, f3);
#pragma unroll
            for (int v = 0; v < VEC; v++) {
                acc[v] += e0.w * f0[v] + e1.w * f1[v];
                acc[v] += e2.w * f2[v] + e3.w * f3[v];
            }
        }
    }
    for (; e < end; e++) {
        Edge e0 = g_edge[e];
        if (act) {
            float f0[VEC];
            ld_half8(hh + (size_t)e0.s * CH + c0, f0);
#pragma unroll
            for (int v = 0; v < VEC; v++) acc[v] += e0.w * f0[v];
        }
    }
    if (act) {
        float* orow = out + (size_t)node * CH + c0;
#pragma unroll
        for (int v = 0; v < VEC; v++) acc[v] += bias[c0 + v];
        *(float4*)&orow[0] = make_float4(acc[0], acc[1], acc[2], acc[3]);
        *(float4*)&orow[4] = make_float4(acc[4], acc[5], acc[6], acc[7]);
    }
}

// ---------------- launch ------------------------------------------------------
extern "C" void kernel_launch(void* const* d_in, const int* in_sizes, int n_in,
                              void* d_out, int out_size) {
    const float* x  = (const float*)d_in[0];
    const int* ei32 = (const int*)d_in[1];
    const float* W1 = (const float*)d_in[2];
    const float* b1 = (const float*)d_in[3];
    const float* W2 = (const float*)d_in[4];
    const float* b2 = (const float*)d_in[5];
    const float* W3 = (const float*)d_in[6];
    const float* b3 = (const float*)d_in[7];
    float* out      = (float*)d_out;
    int E = in_sizes[1] / 2;

    // CSR build
    k_prep<<<NPB, 256>>>(ei32, x, E);
    k_scanall<<<NSB, 256>>>();
    k_scatter<<<(E / 2 + 255) / 256, 256>>>(ei32, E);

    int gMMA = (NN + 127) / 128;  // 782

    // layer 1
    k_agg12<<<(NN * 8 + 255) / 256, 256>>>();
    k_gemm1<<<(NN + 31) / 32, 128>>>(W1, b1);

    // layer 2
    k_agg64<<<(NN * 8 + 255) / 256, 256>>>();
    k_hgemm<64, 128, false, true, true, true><<<gMMA, 256>>>(W2, b2);

    // layer 3
    k_hgemm<128, 96, true, false, false, false><<<gMMA, 256>>>(W3, nullptr);
    k_agg96<<<(NN * 16 + 255) / 256, 256>>>(out, b3);
}